// round 3
// baseline (speedup 1.0000x reference)
#include <cuda_runtime.h>
#include <math.h>

// Problem dims (fixed by reference)
#define NROWS 4096
#define NEMB  2048
#define NHID  1024
#define MM    8
#define DD    512

// Scratch (allocation-free rule: __device__ globals)
__device__ float g_h1[NROWS * NHID];
__device__ float g_h2[NROWS * NHID];
__device__ float g_B [NROWS * 3];

// ---------------------------------------------------------------------------
// SGEMM: C[M,N] = act(A[M,K] @ W[K,N] + bias[N]),  act = ELU or identity
// 128x128 block tile, BK=8, 8x8 per-thread microtile, 256 threads.
// Requires M%128==0, N%128==0, K%8==0 (true for all our shapes).
// ---------------------------------------------------------------------------
template <bool ELU>
__global__ __launch_bounds__(256, 2)
void sgemm_bias_act(int M, int N, int K,
                    const float* __restrict__ A,
                    const float* __restrict__ W,
                    const float* __restrict__ bias,
                    float* __restrict__ C)
{
    constexpr int BM = 128, BN = 128, BK = 8, TM = 8, TN = 8;

    __shared__ __align__(16) float As[BK][BM];  // A stored transposed
    __shared__ __align__(16) float Bs[BK][BN];

    const int tid  = threadIdx.x;
    const int brow = blockIdx.y * BM;
    const int bcol = blockIdx.x * BN;

    // compute-thread coords: 16 x 16 threads, each owns TMxTN
    const int tx = tid % (BN / TN);   // 0..15
    const int ty = tid / (BN / TN);   // 0..15

    // load coords
    const int a_row = tid >> 1;          // 0..127
    const int a_col = (tid & 1) * 4;     // 0 or 4
    const int b_row = tid >> 5;          // 0..7
    const int b_col = (tid & 31) * 4;    // 0..124

    const float* Aptr = A + (size_t)(brow + a_row) * K + a_col;
    const float* Wptr = W + (size_t)b_row * N + bcol + b_col;

    float acc[TM][TN];
#pragma unroll
    for (int i = 0; i < TM; i++)
#pragma unroll
        for (int j = 0; j < TN; j++) acc[i][j] = 0.f;

    for (int k0 = 0; k0 < K; k0 += BK) {
        float4 av = *reinterpret_cast<const float4*>(Aptr + k0);
        As[a_col + 0][a_row] = av.x;
        As[a_col + 1][a_row] = av.y;
        As[a_col + 2][a_row] = av.z;
        As[a_col + 3][a_row] = av.w;

        float4 bv = *reinterpret_cast<const float4*>(Wptr + (size_t)k0 * N);
        *reinterpret_cast<float4*>(&Bs[b_row][b_col]) = bv;

        __syncthreads();

#pragma unroll
        for (int k = 0; k < BK; k++) {
            float ar[TM], br[TN];
            float4 a0 = *reinterpret_cast<const float4*>(&As[k][ty * TM]);
            float4 a1 = *reinterpret_cast<const float4*>(&As[k][ty * TM + 4]);
            ar[0]=a0.x; ar[1]=a0.y; ar[2]=a0.z; ar[3]=a0.w;
            ar[4]=a1.x; ar[5]=a1.y; ar[6]=a1.z; ar[7]=a1.w;
            float4 b0 = *reinterpret_cast<const float4*>(&Bs[k][tx * TN]);
            float4 b1 = *reinterpret_cast<const float4*>(&Bs[k][tx * TN + 4]);
            br[0]=b0.x; br[1]=b0.y; br[2]=b0.z; br[3]=b0.w;
            br[4]=b1.x; br[5]=b1.y; br[6]=b1.z; br[7]=b1.w;
#pragma unroll
            for (int i = 0; i < TM; i++)
#pragma unroll
                for (int j = 0; j < TN; j++)
                    acc[i][j] = fmaf(ar[i], br[j], acc[i][j]);
        }
        __syncthreads();
    }

    // epilogue: bias + (optional) ELU, vectorized stores
#pragma unroll
    for (int i = 0; i < TM; i++) {
        int row = brow + ty * TM + i;
        float* crow = C + (size_t)row * N + bcol + tx * TN;
#pragma unroll
        for (int j4 = 0; j4 < TN; j4 += 4) {
            float4 v;
            const float* bp = bias + bcol + tx * TN + j4;
            float r0 = acc[i][j4+0] + bp[0];
            float r1 = acc[i][j4+1] + bp[1];
            float r2 = acc[i][j4+2] + bp[2];
            float r3 = acc[i][j4+3] + bp[3];
            if (ELU) {
                r0 = r0 > 0.f ? r0 : expm1f(r0);
                r1 = r1 > 0.f ? r1 : expm1f(r1);
                r2 = r2 > 0.f ? r2 : expm1f(r2);
                r3 = r3 > 0.f ? r3 : expm1f(r3);
            }
            v.x=r0; v.y=r1; v.z=r2; v.w=r3;
            *reinterpret_cast<float4*>(crow + j4) = v;
        }
    }
}

// ---------------------------------------------------------------------------
// B[n, 0:3] = h2[n,:] @ W3 + b3     (one warp per row, coalesced along k)
// ---------------------------------------------------------------------------
__global__ __launch_bounds__(256)
void compute_B_kernel(const float* __restrict__ h,
                      const float* __restrict__ W3,
                      const float* __restrict__ b3,
                      float* __restrict__ Bout)
{
    const int warp = (blockIdx.x * blockDim.x + threadIdx.x) >> 5;
    const int lane = threadIdx.x & 31;
    if (warp >= NROWS) return;

    const float* hr = h + (size_t)warp * NHID;
    float a0 = 0.f, a1 = 0.f, a2 = 0.f;
#pragma unroll 4
    for (int k = lane; k < NHID; k += 32) {
        float v = hr[k];
        a0 = fmaf(v, __ldg(&W3[k * 3 + 0]), a0);
        a1 = fmaf(v, __ldg(&W3[k * 3 + 1]), a1);
        a2 = fmaf(v, __ldg(&W3[k * 3 + 2]), a2);
    }
#pragma unroll
    for (int off = 16; off > 0; off >>= 1) {
        a0 += __shfl_down_sync(0xffffffffu, a0, off);
        a1 += __shfl_down_sync(0xffffffffu, a1, off);
        a2 += __shfl_down_sync(0xffffffffu, a2, off);
    }
    if (lane == 0) {
        Bout[warp * 3 + 0] = a0 + b3[0];
        Bout[warp * 3 + 1] = a1 + b3[1];
        Bout[warp * 3 + 2] = a2 + b3[2];
    }
}

// ---------------------------------------------------------------------------
// y[n,m,d] = sum_c B[n,c] * X[n,m,c,d]   (pure bandwidth, float4)
// one block (128 thr) per (n,m); DD/4 = 128 float4 per block
// ---------------------------------------------------------------------------
__global__ __launch_bounds__(128)
void apply_B_kernel(const float* __restrict__ Bm,
                    const float* __restrict__ X,
                    float* __restrict__ Y)
{
    const int nm = blockIdx.x;          // 0 .. NROWS*MM-1
    const int n  = nm >> 3;             // / MM
    const float b0 = __ldg(&Bm[n * 3 + 0]);
    const float b1 = __ldg(&Bm[n * 3 + 1]);
    const float b2 = __ldg(&Bm[n * 3 + 2]);

    const size_t base = (size_t)nm * 3 * DD;
    const float4* x0 = reinterpret_cast<const float4*>(X + base);
    const float4* x1 = reinterpret_cast<const float4*>(X + base + DD);
    const float4* x2 = reinterpret_cast<const float4*>(X + base + 2 * DD);
    float4* y = reinterpret_cast<float4*>(Y + (size_t)nm * DD);

    const int t = threadIdx.x;          // 0..127
    float4 v0 = x0[t], v1 = x1[t], v2 = x2[t];
    float4 r;
    r.x = fmaf(b0, v0.x, fmaf(b1, v1.x, b2 * v2.x));
    r.y = fmaf(b0, v0.y, fmaf(b1, v1.y, b2 * v2.y));
    r.z = fmaf(b0, v0.z, fmaf(b1, v1.z, b2 * v2.z));
    r.w = fmaf(b0, v0.w, fmaf(b1, v1.w, b2 * v2.w));
    y[t] = r;
}

// ---------------------------------------------------------------------------
extern "C" void kernel_launch(void* const* d_in, const int* in_sizes, int n_in,
                              void* d_out, int out_size)
{
    const float* E  = (const float*)d_in[0];  // [4096, 2048]
    const float* X  = (const float*)d_in[1];  // [4096, 8, 3, 512]
    const float* W1 = (const float*)d_in[2];  // [2048, 1024]
    const float* b1 = (const float*)d_in[3];  // [1024]
    const float* W2 = (const float*)d_in[4];  // [1024, 1024]
    const float* b2 = (const float*)d_in[5];  // [1024]
    const float* W3 = (const float*)d_in[6];  // [1024, 3]
    const float* b3 = (const float*)d_in[7];  // [3]
    float* Y = (float*)d_out;                 // [4096, 8, 512]

    float *h1, *h2, *Bs;
    cudaGetSymbolAddress((void**)&h1, g_h1);
    cudaGetSymbolAddress((void**)&h2, g_h2);
    cudaGetSymbolAddress((void**)&Bs, g_B);

    // GEMM1: h1 = elu(E @ W1 + b1)   [4096,2048]x[2048,1024]
    {
        dim3 grid(NHID / 128, NROWS / 128);
        sgemm_bias_act<true><<<grid, 256>>>(NROWS, NHID, NEMB, E, W1, b1, h1);
    }
    // GEMM2: h2 = elu(h1 @ W2 + b2)  [4096,1024]x[1024,1024]
    {
        dim3 grid(NHID / 128, NROWS / 128);
        sgemm_bias_act<true><<<grid, 256>>>(NROWS, NHID, NHID, h1, W2, b2, h2);
    }
    // B = h2 @ W3 + b3               [4096,1024]x[1024,3]
    compute_B_kernel<<<(NROWS * 32) / 256, 256>>>(h2, W3, b3, Bs);

    // y = einsum("nc,nmcd->nmd", B, X)
    apply_B_kernel<<<NROWS * MM, 128>>>(Bs, X, Y);
}

// round 7
// speedup vs baseline: 1.9283x; 1.9283x over previous
#include <cuda_runtime.h>
#include <cuda_bf16.h>
#include <math.h>
#include <stdint.h>

// Problem dims (fixed)
#define NROWS 4096
#define NEMB  2048
#define NHID  1024
#define MM    8
#define DD    512

// ---------------------------------------------------------------------------
// Scratch (__device__ globals; no allocation allowed)
// ---------------------------------------------------------------------------
__device__ __align__(256) __nv_bfloat16 g_Ehi [NROWS * NEMB];
__device__ __align__(256) __nv_bfloat16 g_Elo [NROWS * NEMB];
__device__ __align__(256) __nv_bfloat16 g_W1hi[NHID * NEMB];   // transposed [N=1024][K=2048]
__device__ __align__(256) __nv_bfloat16 g_W1lo[NHID * NEMB];
__device__ __align__(256) __nv_bfloat16 g_W2hi[NHID * NHID];   // transposed [N=1024][K=1024]
__device__ __align__(256) __nv_bfloat16 g_W2lo[NHID * NHID];
__device__ __align__(256) __nv_bfloat16 g_h1hi[NROWS * NHID];
__device__ __align__(256) __nv_bfloat16 g_h1lo[NROWS * NHID];
__device__ __align__(256) float         g_h2  [NROWS * NHID];
__device__ __align__(256) float         g_B   [NROWS * 3];

// ---------------------------------------------------------------------------
// Helpers (baseline PTX only: ldmatrix / mma.sync / cp.async — legal on sm_100)
// ---------------------------------------------------------------------------
__device__ __forceinline__ uint32_t smem_u32(const void* p) {
    uint32_t a;
    asm("{ .reg .u64 t; cvta.to.shared.u64 t, %1; cvt.u32.u64 %0, t; }" : "=r"(a) : "l"(p));
    return a;
}
__device__ __forceinline__ void ldsm_x4(uint32_t* r, uint32_t addr) {
    asm volatile("ldmatrix.sync.aligned.m8n8.x4.shared.b16 {%0,%1,%2,%3}, [%4];"
        : "=r"(r[0]), "=r"(r[1]), "=r"(r[2]), "=r"(r[3]) : "r"(addr));
}
__device__ __forceinline__ void mma16816(float* c, const uint32_t* a, const uint32_t* b) {
    asm volatile("mma.sync.aligned.m16n8k16.row.col.f32.bf16.bf16.f32 "
        "{%0,%1,%2,%3}, {%4,%5,%6,%7}, {%8,%9}, {%0,%1,%2,%3};"
        : "+f"(c[0]), "+f"(c[1]), "+f"(c[2]), "+f"(c[3])
        : "r"(a[0]), "r"(a[1]), "r"(a[2]), "r"(a[3]), "r"(b[0]), "r"(b[1]));
}

// ---------------------------------------------------------------------------
// fp32 -> bf16 hi/lo split, elementwise (for E)
// ---------------------------------------------------------------------------
__global__ __launch_bounds__(256)
void split2_kernel(const float2* __restrict__ in,
                   __nv_bfloat162* __restrict__ hi,
                   __nv_bfloat162* __restrict__ lo, int n2)
{
    int i = blockIdx.x * blockDim.x + threadIdx.x;
    if (i >= n2) return;
    float2 v = in[i];
    __nv_bfloat16 h0 = __float2bfloat16(v.x);
    __nv_bfloat16 h1 = __float2bfloat16(v.y);
    __nv_bfloat162 H; H.x = h0; H.y = h1;
    __nv_bfloat162 L;
    L.x = __float2bfloat16(v.x - __bfloat162float(h0));
    L.y = __float2bfloat16(v.y - __bfloat162float(h1));
    hi[i] = H; lo[i] = L;
}

// ---------------------------------------------------------------------------
// W [K,N] fp32 -> transposed split Thi/Tlo [N][K] bf16 (tiled 32x32)
// ---------------------------------------------------------------------------
__global__ __launch_bounds__(256)
void transpose_split_kernel(const float* __restrict__ W,
                            __nv_bfloat16* __restrict__ Thi,
                            __nv_bfloat16* __restrict__ Tlo, int K, int N)
{
    __shared__ float tile[32][33];
    const int n0 = blockIdx.x * 32, k0 = blockIdx.y * 32;
    const int tx = threadIdx.x, ty = threadIdx.y;
#pragma unroll
    for (int r = ty; r < 32; r += 8)
        tile[r][tx] = W[(size_t)(k0 + r) * N + n0 + tx];
    __syncthreads();
#pragma unroll
    for (int r = ty; r < 32; r += 8) {
        float v = tile[tx][r];                 // = W[k0+tx][n0+r]
        size_t o = (size_t)(n0 + r) * K + k0 + tx;
        __nv_bfloat16 h = __float2bfloat16(v);
        Thi[o] = h;
        Tlo[o] = __float2bfloat16(v - __bfloat162float(h));
    }
}

// ---------------------------------------------------------------------------
// mma.sync GEMM:  C[128,128] per CTA = (Ahi+Alo) @ (Bhi+Blo)^T, 3 products.
// A: [M,KDIM] bf16 K-major (hi/lo).  B: [N,KDIM] bf16 K-major (pre-transposed W).
// smem row layout per tile row r: [hi k0..31 | lo k0..31] = 128B, SW128 XOR swizzle.
// 3-stage cp.async pipeline. 8 warps (2m x 4n), warp tile 64x32.
// Epilogue: +bias, ELU; OUT_SPLIT -> bf16 hi/lo, else fp32.
// ---------------------------------------------------------------------------
#define GEMM_SMEM_BYTES (3 * 32768)

template<int KDIM, bool OUT_SPLIT>
__global__ __launch_bounds__(256)
void mma_gemm(const __nv_bfloat16* __restrict__ Ahi, const __nv_bfloat16* __restrict__ Alo,
              const __nv_bfloat16* __restrict__ Bhi, const __nv_bfloat16* __restrict__ Blo,
              const float* __restrict__ bias,
              __nv_bfloat16* __restrict__ Ohi, __nv_bfloat16* __restrict__ Olo,
              float* __restrict__ Of)
{
    extern __shared__ char smem[];
    const uint32_t sbase = smem_u32(smem);

    const int tid = threadIdx.x, wid = tid >> 5, lane = tid & 31;
    const int brow = blockIdx.y * 128, bcol = blockIdx.x * 128;
    const int wm = wid >> 2, wn = wid & 3;   // 2 x 4 warp grid; warp tile 64m x 32n

    constexpr int NIT = KDIM / 32;
    constexpr int STAGE = 32768;             // A tile 16KB + B tile 16KB

    float acc[4][4][4];
#pragma unroll
    for (int i = 0; i < 4; i++)
#pragma unroll
        for (int j = 0; j < 4; j++)
#pragma unroll
            for (int k = 0; k < 4; k++) acc[i][j][k] = 0.f;

    // stage loader: 1024 16B-chunks per operand; chunk c<4 = hi k-octet c, c>=4 = lo
    auto load_stage = [&](int it, int s) {
        const int k0 = it * 32;
        const uint32_t as = sbase + s * STAGE;
        const uint32_t bs = as + 16384;
#pragma unroll
        for (int t = 0; t < 4; t++) {
            int ci = tid + t * 256;
            int r = ci >> 3, c = ci & 7;
            uint32_t dst = ((uint32_t)(r * 128 + c * 16)) ^ ((uint32_t)(r & 7) << 4);
            const __nv_bfloat16* ga = (c < 4)
                ? Ahi + (size_t)(brow + r) * KDIM + k0 + c * 8
                : Alo + (size_t)(brow + r) * KDIM + k0 + (c - 4) * 8;
            const __nv_bfloat16* gb = (c < 4)
                ? Bhi + (size_t)(bcol + r) * KDIM + k0 + c * 8
                : Blo + (size_t)(bcol + r) * KDIM + k0 + (c - 4) * 8;
            asm volatile("cp.async.cg.shared.global [%0], [%1], 16;" :: "r"(as + dst), "l"(ga) : "memory");
            asm volatile("cp.async.cg.shared.global [%0], [%1], 16;" :: "r"(bs + dst), "l"(gb) : "memory");
        }
        asm volatile("cp.async.commit_group;" ::: "memory");
    };

    load_stage(0, 0);
    load_stage(1, 1);

    // ldmatrix per-lane logical coords
    const int a_row = lane & 15;            // row within 16-row fragment
    const int a_kc  = lane >> 4;            // k-octet 0/1 within k16
    const int b_row = (lane & 7) + ((lane >> 4) << 3);  // n within 16
    const int b_kc  = (lane >> 3) & 1;

    for (int it = 0; it < NIT; it++) {
        if (it + 2 < NIT) asm volatile("cp.async.wait_group 1;" ::: "memory");
        else              asm volatile("cp.async.wait_group 0;" ::: "memory");
        __syncthreads();
        if (it + 2 < NIT) load_stage(it + 2, (it + 2) % 3);

        const uint32_t as = sbase + (it % 3) * STAGE;
        const uint32_t bs = as + 16384;

#pragma unroll
        for (int ks = 0; ks < 2; ks++) {
            uint32_t Ah[4][4], Al[4][4];
#pragma unroll
            for (int mf = 0; mf < 4; mf++) {
                int r = wm * 64 + mf * 16 + a_row;
                int ch = ks * 2 + a_kc;
                uint32_t oh = ((uint32_t)(r * 128 + ch * 16))       ^ ((uint32_t)(r & 7) << 4);
                uint32_t ol = ((uint32_t)(r * 128 + (ch + 4) * 16)) ^ ((uint32_t)(r & 7) << 4);
                ldsm_x4(Ah[mf], as + oh);
                ldsm_x4(Al[mf], as + ol);
            }
            uint32_t Bh[2][4], Bl[2][4];
#pragma unroll
            for (int nf = 0; nf < 2; nf++) {
                int r = wn * 32 + nf * 16 + b_row;
                int ch = ks * 2 + b_kc;
                uint32_t oh = ((uint32_t)(r * 128 + ch * 16))       ^ ((uint32_t)(r & 7) << 4);
                uint32_t ol = ((uint32_t)(r * 128 + (ch + 4) * 16)) ^ ((uint32_t)(r & 7) << 4);
                ldsm_x4(Bh[nf], bs + oh);
                ldsm_x4(Bl[nf], bs + ol);
            }
#pragma unroll
            for (int mf = 0; mf < 4; mf++)
#pragma unroll
                for (int nf = 0; nf < 4; nf++) {
                    const uint32_t* bh = &Bh[nf >> 1][(nf & 1) * 2];
                    const uint32_t* bl = &Bl[nf >> 1][(nf & 1) * 2];
                    mma16816(acc[mf][nf], Ah[mf], bh);   // hi*hi
                    mma16816(acc[mf][nf], Ah[mf], bl);   // hi*lo
                    mma16816(acc[mf][nf], Al[mf], bh);   // lo*hi
                }
        }
    }

    // Epilogue: c-frag m16n8 layout: c0,c1 @ (row=lane>>2, col=(lane&3)*2); c2,c3 @ row+8
    const int erow = lane >> 2, ecol = (lane & 3) * 2;
#pragma unroll
    for (int mf = 0; mf < 4; mf++) {
#pragma unroll
        for (int nf = 0; nf < 4; nf++) {
            int col = bcol + wn * 32 + nf * 8 + ecol;
            float bv0 = bias[col], bv1 = bias[col + 1];
#pragma unroll
            for (int half = 0; half < 2; half++) {
                int row = brow + wm * 64 + mf * 16 + erow + half * 8;
                float v0 = acc[mf][nf][half * 2 + 0] + bv0;
                float v1 = acc[mf][nf][half * 2 + 1] + bv1;
                v0 = v0 > 0.f ? v0 : expm1f(v0);
                v1 = v1 > 0.f ? v1 : expm1f(v1);
                size_t o = (size_t)row * NHID + col;
                if (OUT_SPLIT) {
                    __nv_bfloat16 h0 = __float2bfloat16(v0);
                    __nv_bfloat16 h1 = __float2bfloat16(v1);
                    Ohi[o]     = h0;
                    Ohi[o + 1] = h1;
                    Olo[o]     = __float2bfloat16(v0 - __bfloat162float(h0));
                    Olo[o + 1] = __float2bfloat16(v1 - __bfloat162float(h1));
                } else {
                    Of[o]     = v0;
                    Of[o + 1] = v1;
                }
            }
        }
    }
}

// ---------------------------------------------------------------------------
// B[n,0:3] = h2[n,:] @ W3 + b3   (one warp per row)
// ---------------------------------------------------------------------------
__global__ __launch_bounds__(256)
void compute_B_kernel(const float* __restrict__ h,
                      const float* __restrict__ W3,
                      const float* __restrict__ b3,
                      float* __restrict__ Bout)
{
    const int warp = (blockIdx.x * blockDim.x + threadIdx.x) >> 5;
    const int lane = threadIdx.x & 31;
    if (warp >= NROWS) return;
    const float* hr = h + (size_t)warp * NHID;
    float a0 = 0.f, a1 = 0.f, a2 = 0.f;
#pragma unroll 4
    for (int k = lane; k < NHID; k += 32) {
        float v = hr[k];
        a0 = fmaf(v, __ldg(&W3[k * 3 + 0]), a0);
        a1 = fmaf(v, __ldg(&W3[k * 3 + 1]), a1);
        a2 = fmaf(v, __ldg(&W3[k * 3 + 2]), a2);
    }
#pragma unroll
    for (int off = 16; off > 0; off >>= 1) {
        a0 += __shfl_down_sync(0xffffffffu, a0, off);
        a1 += __shfl_down_sync(0xffffffffu, a1, off);
        a2 += __shfl_down_sync(0xffffffffu, a2, off);
    }
    if (lane == 0) {
        Bout[warp * 3 + 0] = a0 + b3[0];
        Bout[warp * 3 + 1] = a1 + b3[1];
        Bout[warp * 3 + 2] = a2 + b3[2];
    }
}

// ---------------------------------------------------------------------------
// y[n,m,d] = sum_c B[n,c] * X[n,m,c,d]   (bandwidth-bound; measured 81% HBM)
// ---------------------------------------------------------------------------
__global__ __launch_bounds__(128)
void apply_B_kernel(const float* __restrict__ Bm,
                    const float* __restrict__ X,
                    float* __restrict__ Y)
{
    const int nm = blockIdx.x;
    const int n  = nm >> 3;
    const float b0 = __ldg(&Bm[n * 3 + 0]);
    const float b1 = __ldg(&Bm[n * 3 + 1]);
    const float b2 = __ldg(&Bm[n * 3 + 2]);
    const size_t base = (size_t)nm * 3 * DD;
    const float4* x0 = reinterpret_cast<const float4*>(X + base);
    const float4* x1 = reinterpret_cast<const float4*>(X + base + DD);
    const float4* x2 = reinterpret_cast<const float4*>(X + base + 2 * DD);
    float4* y = reinterpret_cast<float4*>(Y + (size_t)nm * DD);
    const int t = threadIdx.x;
    float4 v0 = x0[t], v1 = x1[t], v2 = x2[t];
    float4 r;
    r.x = fmaf(b0, v0.x, fmaf(b1, v1.x, b2 * v2.x));
    r.y = fmaf(b0, v0.y, fmaf(b1, v1.y, b2 * v2.y));
    r.z = fmaf(b0, v0.z, fmaf(b1, v1.z, b2 * v2.z));
    r.w = fmaf(b0, v0.w, fmaf(b1, v1.w, b2 * v2.w));
    y[t] = r;
}

// ---------------------------------------------------------------------------
extern "C" void kernel_launch(void* const* d_in, const int* in_sizes, int n_in,
                              void* d_out, int out_size)
{
    const float* E  = (const float*)d_in[0];
    const float* X  = (const float*)d_in[1];
    const float* W1 = (const float*)d_in[2];
    const float* b1 = (const float*)d_in[3];
    const float* W2 = (const float*)d_in[4];
    const float* b2 = (const float*)d_in[5];
    const float* W3 = (const float*)d_in[6];
    const float* b3 = (const float*)d_in[7];
    float* Y = (float*)d_out;

    __nv_bfloat16 *Ehi, *Elo, *W1hi, *W1lo, *W2hi, *W2lo, *h1hi, *h1lo;
    float *h2, *Bs;
    cudaGetSymbolAddress((void**)&Ehi,  g_Ehi);
    cudaGetSymbolAddress((void**)&Elo,  g_Elo);
    cudaGetSymbolAddress((void**)&W1hi, g_W1hi);
    cudaGetSymbolAddress((void**)&W1lo, g_W1lo);
    cudaGetSymbolAddress((void**)&W2hi, g_W2hi);
    cudaGetSymbolAddress((void**)&W2lo, g_W2lo);
    cudaGetSymbolAddress((void**)&h1hi, g_h1hi);
    cudaGetSymbolAddress((void**)&h1lo, g_h1lo);
    cudaGetSymbolAddress((void**)&h2,   g_h2);
    cudaGetSymbolAddress((void**)&Bs,   g_B);

    cudaFuncSetAttribute(mma_gemm<NEMB, true>,  cudaFuncAttributeMaxDynamicSharedMemorySize, GEMM_SMEM_BYTES);
    cudaFuncSetAttribute(mma_gemm<NHID, false>, cudaFuncAttributeMaxDynamicSharedMemorySize, GEMM_SMEM_BYTES);

    // Prologue: splits
    {
        int n2 = NROWS * NEMB / 2;
        split2_kernel<<<(n2 + 255) / 256, 256>>>((const float2*)E,
                                                 (__nv_bfloat162*)Ehi, (__nv_bfloat162*)Elo, n2);
    }
    transpose_split_kernel<<<dim3(NHID / 32, NEMB / 32), dim3(32, 8)>>>(W1, W1hi, W1lo, NEMB, NHID);
    transpose_split_kernel<<<dim3(NHID / 32, NHID / 32), dim3(32, 8)>>>(W2, W2hi, W2lo, NHID, NHID);

    // GEMM1: h1 = elu(E @ W1 + b1), emitted as bf16 hi/lo
    mma_gemm<NEMB, true><<<dim3(NHID / 128, NROWS / 128), 256, GEMM_SMEM_BYTES>>>(
        Ehi, Elo, W1hi, W1lo, b1, h1hi, h1lo, nullptr);

    // GEMM2: h2 = elu(h1 @ W2 + b2), fp32
    mma_gemm<NHID, false><<<dim3(NHID / 128, NROWS / 128), 256, GEMM_SMEM_BYTES>>>(
        h1hi, h1lo, W2hi, W2lo, b2, nullptr, nullptr, h2);

    // B = h2 @ W3 + b3
    compute_B_kernel<<<(NROWS * 32) / 256, 256>>>(h2, W3, b3, Bs);

    // y = einsum("nc,nmcd->nmd", B, X)
    apply_B_kernel<<<NROWS * MM, 128>>>(Bs, X, Y);
}